// round 1
// baseline (speedup 1.0000x reference)
#include <cuda_runtime.h>

// ============================================================================
// Triaffine: s[b,z,x,y] = sum_{i,k,j} xb[b,x,i] * z[b,z,k] * W[i,k,j] * yb[b,y,j]
//   B=8, S=128, D=512, I=J=513 (bias), K=512, W layout [i][k][j] row-major.
// 3 stages, all fp32 with packed fma.rn.f32x2 (B300: 3-reg FFMA is half-rate;
// f32x2 restores 128 FMA/cyc/SM).
//   k1: Xw[bx, k*513+j] = xb_all[1024,513] @ W[513, 262656]
//   k2: T[bx, z, j]     = z[b][128,512]    @ Xw[bx][512,513]
//   k3: out[b,z,x,y]    = T[bx][128,513]   @ yb[b][128,513]^T
// ============================================================================

#define BM 128
#define BN 128
#define BK 16

#define NIN   512
#define IDIM  513                 // NIN + bias
#define NW    262656              // 512*513  (k,j) flattened
#define TROW  65664               // 128*513

// Scratch (device globals — allocation-free per harness rules)
__device__ float g_Xw[268959744]; // 1024 * 262656 floats (~1.08 GB)
__device__ float g_T [67239936];  // 1024 * 128 * 513 floats (~269 MB)

static __device__ __forceinline__ unsigned long long pack2(float v) {
    unsigned long long r;
    unsigned u = __float_as_uint(v);
    asm("mov.b64 %0, {%1, %1};" : "=l"(r) : "r"(u));
    return r;
}

// 8x8 per-thread micro-kernel over a BK slice, packed f32x2 accumulation.
// acc[i][j] packs output columns (2j, 2j+1) for row i.
static __device__ __forceinline__ void mma_step(
    const float (&As)[BK][BM], const float (&Bs)[BK][BN],
    unsigned long long (&acc)[8][4], int tx, int ty)
{
#pragma unroll
    for (int kk = 0; kk < BK; kk++) {
        float4 a0 = *reinterpret_cast<const float4*>(&As[kk][ty * 8]);
        float4 a1 = *reinterpret_cast<const float4*>(&As[kk][ty * 8 + 4]);
        ulonglong2 b0 = *reinterpret_cast<const ulonglong2*>(&Bs[kk][tx * 8]);
        ulonglong2 b1 = *reinterpret_cast<const ulonglong2*>(&Bs[kk][tx * 8 + 4]);
        unsigned long long bp0 = b0.x, bp1 = b0.y, bp2 = b1.x, bp3 = b1.y;
        float av[8] = {a0.x, a0.y, a0.z, a0.w, a1.x, a1.y, a1.z, a1.w};
#pragma unroll
        for (int i = 0; i < 8; i++) {
            unsigned long long ap = pack2(av[i]);
            asm("fma.rn.f32x2 %0, %1, %2, %0;" : "+l"(acc[i][0]) : "l"(ap), "l"(bp0));
            asm("fma.rn.f32x2 %0, %1, %2, %0;" : "+l"(acc[i][1]) : "l"(ap), "l"(bp1));
            asm("fma.rn.f32x2 %0, %1, %2, %0;" : "+l"(acc[i][2]) : "l"(ap), "l"(bp2));
            asm("fma.rn.f32x2 %0, %1, %2, %0;" : "+l"(acc[i][3]) : "l"(ap), "l"(bp3));
        }
    }
}

// ----------------------------------------------------------------------------
// k1: Xw = xb_all @ W.  grid = (8 m-tiles, 2052 n-tiles) — m fastest so the 8
// CTAs sharing one W column-panel are wave-adjacent (W read ~once from DRAM).
// ----------------------------------------------------------------------------
__global__ __launch_bounds__(256, 2)
void triaffine_k1(const float* __restrict__ x, const float* __restrict__ W)
{
    __shared__ float As[BK][BM];
    __shared__ float Bs[BK][BN];
    const int       m0 = blockIdx.x * BM;
    const long long n0 = (long long)blockIdx.y * BN;
    const int tid = threadIdx.x;
    const int tx = tid & 15, ty = tid >> 4;
    const int a_row = tid >> 1;
    const int a_k   = (tid & 1) * 8;
    const int b_row = tid >> 4;
    const int b_col = (tid & 15) * 8;

    unsigned long long acc[8][4];
#pragma unroll
    for (int i = 0; i < 8; i++)
#pragma unroll
        for (int j = 0; j < 4; j++) acc[i][j] = 0ull;

    const long long arow = (long long)(m0 + a_row) * NIN;

    for (int k0 = 0; k0 < IDIM; k0 += BK) {
        // A (xb, virtual bias column) -> As transposed
        if (k0 + a_k + 7 < NIN) {
            float4 v0 = *reinterpret_cast<const float4*>(x + arow + k0 + a_k);
            float4 v1 = *reinterpret_cast<const float4*>(x + arow + k0 + a_k + 4);
            As[a_k + 0][a_row] = v0.x; As[a_k + 1][a_row] = v0.y;
            As[a_k + 2][a_row] = v0.z; As[a_k + 3][a_row] = v0.w;
            As[a_k + 4][a_row] = v1.x; As[a_k + 5][a_row] = v1.y;
            As[a_k + 6][a_row] = v1.z; As[a_k + 7][a_row] = v1.w;
        } else {
#pragma unroll
            for (int u = 0; u < 8; u++) {
                int i = k0 + a_k + u;
                float v = (i < NIN) ? x[arow + i] : (i == NIN ? 1.0f : 0.0f);
                As[a_k + u][a_row] = v;
            }
        }
        // B (W row i, contiguous along n)
        {
            int i = k0 + b_row;
            if (i < IDIM) {
                const float* p = W + (long long)i * NW + n0 + b_col;
                float4 v0 = *reinterpret_cast<const float4*>(p);
                float4 v1 = *reinterpret_cast<const float4*>(p + 4);
                *reinterpret_cast<float4*>(&Bs[b_row][b_col])     = v0;
                *reinterpret_cast<float4*>(&Bs[b_row][b_col + 4]) = v1;
            } else {
                float4 zz = make_float4(0.f, 0.f, 0.f, 0.f);
                *reinterpret_cast<float4*>(&Bs[b_row][b_col])     = zz;
                *reinterpret_cast<float4*>(&Bs[b_row][b_col + 4]) = zz;
            }
        }
        __syncthreads();
        mma_step(As, Bs, acc, tx, ty);
        __syncthreads();
    }

#pragma unroll
    for (int i = 0; i < 8; i++) {
        float* crow = g_Xw + (long long)(m0 + ty * 8 + i) * NW + n0 + tx * 8;
        ulonglong2 r0; r0.x = acc[i][0]; r0.y = acc[i][1];
        ulonglong2 r1; r1.x = acc[i][2]; r1.y = acc[i][3];
        *reinterpret_cast<ulonglong2*>(crow)     = r0;
        *reinterpret_cast<ulonglong2*>(crow + 4) = r1;
    }
}

// ----------------------------------------------------------------------------
// k2: T[bx] = z[b] @ Xw[bx].  grid = (5 n-tiles, 1024 bx). N=513 -> guarded.
// ----------------------------------------------------------------------------
__global__ __launch_bounds__(256, 2)
void triaffine_k2(const float* __restrict__ zin)
{
    __shared__ float As[BK][BM];
    __shared__ float Bs[BK][BN];
    const int bx = blockIdx.y;
    const int b  = bx >> 7;
    const int n0 = blockIdx.x * BN;
    const int tid = threadIdx.x;
    const int tx = tid & 15, ty = tid >> 4;
    const int a_row = tid >> 1;
    const int a_k   = (tid & 1) * 8;
    const int b_row = tid >> 4;
    const int b_col = (tid & 15) * 8;

    unsigned long long acc[8][4];
#pragma unroll
    for (int i = 0; i < 8; i++)
#pragma unroll
        for (int j = 0; j < 4; j++) acc[i][j] = 0ull;

    const long long zrow  = ((long long)b * 128 + a_row) * NIN;
    const float*    Bbase = g_Xw + (long long)bx * NW;

    for (int k0 = 0; k0 < NIN; k0 += BK) {
        float4 v0 = *reinterpret_cast<const float4*>(zin + zrow + k0 + a_k);
        float4 v1 = *reinterpret_cast<const float4*>(zin + zrow + k0 + a_k + 4);
        As[a_k + 0][a_row] = v0.x; As[a_k + 1][a_row] = v0.y;
        As[a_k + 2][a_row] = v0.z; As[a_k + 3][a_row] = v0.w;
        As[a_k + 4][a_row] = v1.x; As[a_k + 5][a_row] = v1.y;
        As[a_k + 6][a_row] = v1.z; As[a_k + 7][a_row] = v1.w;
        {
            const float* p = Bbase + (long long)(k0 + b_row) * IDIM + n0 + b_col;
#pragma unroll
            for (int u = 0; u < 8; u++) {
                int n = n0 + b_col + u;
                Bs[b_row][b_col + u] = (n < IDIM) ? p[u] : 0.0f;
            }
        }
        __syncthreads();
        mma_step(As, Bs, acc, tx, ty);
        __syncthreads();
    }

    float* Tb = g_T + (long long)bx * TROW;
#pragma unroll
    for (int i = 0; i < 8; i++) {
        int zz = ty * 8 + i;
#pragma unroll
        for (int j = 0; j < 4; j++) {
            int c0 = n0 + tx * 8 + 2 * j;
            float lo = __uint_as_float((unsigned)(acc[i][j] & 0xffffffffull));
            float hi = __uint_as_float((unsigned)(acc[i][j] >> 32));
            if (c0 < IDIM)     Tb[zz * IDIM + c0]     = lo;
            if (c0 + 1 < IDIM) Tb[zz * IDIM + c0 + 1] = hi;
        }
    }
}

// ----------------------------------------------------------------------------
// k3: out[b,z,xx,y] = T[bx] @ yb[b]^T.  grid = 1024 bx, one 128x128 tile each.
// ----------------------------------------------------------------------------
__global__ __launch_bounds__(256, 2)
void triaffine_k3(const float* __restrict__ yin, float* __restrict__ out)
{
    __shared__ float As[BK][BM];
    __shared__ float Bs[BK][BN];
    const int bx = blockIdx.x;
    const int b  = bx >> 7;
    const int xx = bx & 127;
    const int tid = threadIdx.x;
    const int tx = tid & 15, ty = tid >> 4;
    const int a_row = tid >> 1;
    const int a_k   = (tid & 1) * 8;

    unsigned long long acc[8][4];
#pragma unroll
    for (int i = 0; i < 8; i++)
#pragma unroll
        for (int j = 0; j < 4; j++) acc[i][j] = 0ull;

    const float*    Ta   = g_T + (long long)bx * TROW + (long long)a_row * IDIM;
    const long long yrow = ((long long)b * 128 + a_row) * NIN;

    for (int k0 = 0; k0 < IDIM; k0 += BK) {
#pragma unroll
        for (int u = 0; u < 8; u++) {
            int j = k0 + a_k + u;
            As[a_k + u][a_row] = (j < IDIM) ? Ta[j] : 0.0f;
            float bv;
            if (j < NIN)       bv = yin[yrow + j];
            else               bv = (j == NIN) ? 1.0f : 0.0f;
            Bs[a_k + u][a_row] = bv;
        }
        __syncthreads();
        mma_step(As, Bs, acc, tx, ty);
        __syncthreads();
    }

#pragma unroll
    for (int i = 0; i < 8; i++) {
        int zz = ty * 8 + i;
        float* o = out + ((((long long)b * 128 + zz) * 128) + xx) * 128 + tx * 8;
        ulonglong2 r0; r0.x = acc[i][0]; r0.y = acc[i][1];
        ulonglong2 r1; r1.x = acc[i][2]; r1.y = acc[i][3];
        *reinterpret_cast<ulonglong2*>(o)     = r0;
        *reinterpret_cast<ulonglong2*>(o + 4) = r1;
    }
}

// ----------------------------------------------------------------------------

extern "C" void kernel_launch(void* const* d_in, const int* in_sizes, int n_in,
                              void* d_out, int out_size)
{
    const float* x = (const float*)d_in[0];
    const float* y = (const float*)d_in[1];
    const float* z = (const float*)d_in[2];
    const float* w = (const float*)d_in[3];
    float* out = (float*)d_out;

    // Stage 1: Xw = xb_all @ W   (276 GFLOP)
    triaffine_k1<<<dim3(8, 2052), 256>>>(x, w);
    // Stage 2: T[bx] = z[b] @ Xw[bx]   (69 GFLOP)
    triaffine_k2<<<dim3(5, 1024), 256>>>(z);
    // Stage 3: out = T @ yb^T   (17 GFLOP)
    triaffine_k3<<<dim3(1024), 256>>>(y, out);
}

// round 2
// speedup vs baseline: 1.0006x; 1.0006x over previous
#include <cuda_runtime.h>

// ============================================================================
// Triaffine: s[b,z,x,y] = sum_{i,k,j} xb[b,x,i] * z[b,z,k] * W[i,k,j] * yb[b,y,j]
//   B=8, S=128, D=512, I=J=513 (bias), K=512, W layout [i][k][j] row-major.
// 3 stages, all fp32 with packed fma.rn.f32x2 (B300: 3-reg FFMA is half-rate;
// f32x2 restores 128 FMA/cyc/SM).
//   k1: Xw[bx, k*513+j] = xb_all[1024,513] @ W[513, 262656]
//   k2: T[bx, z, j]     = z[b][128,512]    @ Xw[bx][512,513]
//   k3: out[b,z,x,y]    = T[bx][128,513]   @ yb[b][128,513]^T
// ============================================================================

#define BM 128
#define BN 128
#define BK 16

#define NIN   512
#define IDIM  513                 // NIN + bias
#define NW    262656              // 512*513  (k,j) flattened
#define TROW  65664               // 128*513

// Scratch (device globals — allocation-free per harness rules)
__device__ float g_Xw[268959744]; // 1024 * 262656 floats (~1.08 GB)
__device__ float g_T [67239936];  // 1024 * 128 * 513 floats (~269 MB)

static __device__ __forceinline__ unsigned long long pack2(float v) {
    unsigned long long r;
    unsigned u = __float_as_uint(v);
    asm("mov.b64 %0, {%1, %1};" : "=l"(r) : "r"(u));
    return r;
}

// 8x8 per-thread micro-kernel over a BK slice, packed f32x2 accumulation.
// acc[i][j] packs output columns (2j, 2j+1) for row i.
static __device__ __forceinline__ void mma_step(
    const float (&As)[BK][BM], const float (&Bs)[BK][BN],
    unsigned long long (&acc)[8][4], int tx, int ty)
{
#pragma unroll
    for (int kk = 0; kk < BK; kk++) {
        float4 a0 = *reinterpret_cast<const float4*>(&As[kk][ty * 8]);
        float4 a1 = *reinterpret_cast<const float4*>(&As[kk][ty * 8 + 4]);
        ulonglong2 b0 = *reinterpret_cast<const ulonglong2*>(&Bs[kk][tx * 8]);
        ulonglong2 b1 = *reinterpret_cast<const ulonglong2*>(&Bs[kk][tx * 8 + 4]);
        unsigned long long bp0 = b0.x, bp1 = b0.y, bp2 = b1.x, bp3 = b1.y;
        float av[8] = {a0.x, a0.y, a0.z, a0.w, a1.x, a1.y, a1.z, a1.w};
#pragma unroll
        for (int i = 0; i < 8; i++) {
            unsigned long long ap = pack2(av[i]);
            asm("fma.rn.f32x2 %0, %1, %2, %0;" : "+l"(acc[i][0]) : "l"(ap), "l"(bp0));
            asm("fma.rn.f32x2 %0, %1, %2, %0;" : "+l"(acc[i][1]) : "l"(ap), "l"(bp1));
            asm("fma.rn.f32x2 %0, %1, %2, %0;" : "+l"(acc[i][2]) : "l"(ap), "l"(bp2));
            asm("fma.rn.f32x2 %0, %1, %2, %0;" : "+l"(acc[i][3]) : "l"(ap), "l"(bp3));
        }
    }
}

// ----------------------------------------------------------------------------
// k1: Xw = xb_all @ W.  grid = (8 m-tiles, 2052 n-tiles) — m fastest so the 8
// CTAs sharing one W column-panel are wave-adjacent (W read ~once from DRAM).
// ----------------------------------------------------------------------------
__global__ __launch_bounds__(256, 2)
void triaffine_k1(const float* __restrict__ x, const float* __restrict__ W)
{
    __shared__ float As[BK][BM];
    __shared__ float Bs[BK][BN];
    const int       m0 = blockIdx.x * BM;
    const long long n0 = (long long)blockIdx.y * BN;
    const int tid = threadIdx.x;
    const int tx = tid & 15, ty = tid >> 4;
    const int a_row = tid >> 1;
    const int a_k   = (tid & 1) * 8;
    const int b_row = tid >> 4;
    const int b_col = (tid & 15) * 8;

    unsigned long long acc[8][4];
#pragma unroll
    for (int i = 0; i < 8; i++)
#pragma unroll
        for (int j = 0; j < 4; j++) acc[i][j] = 0ull;

    const long long arow = (long long)(m0 + a_row) * NIN;

    for (int k0 = 0; k0 < IDIM; k0 += BK) {
        // A (xb, virtual bias column) -> As transposed
        if (k0 + a_k + 7 < NIN) {
            float4 v0 = *reinterpret_cast<const float4*>(x + arow + k0 + a_k);
            float4 v1 = *reinterpret_cast<const float4*>(x + arow + k0 + a_k + 4);
            As[a_k + 0][a_row] = v0.x; As[a_k + 1][a_row] = v0.y;
            As[a_k + 2][a_row] = v0.z; As[a_k + 3][a_row] = v0.w;
            As[a_k + 4][a_row] = v1.x; As[a_k + 5][a_row] = v1.y;
            As[a_k + 6][a_row] = v1.z; As[a_k + 7][a_row] = v1.w;
        } else {
#pragma unroll
            for (int u = 0; u < 8; u++) {
                int i = k0 + a_k + u;
                float v = (i < NIN) ? x[arow + i] : (i == NIN ? 1.0f : 0.0f);
                As[a_k + u][a_row] = v;
            }
        }
        // B (W row i, contiguous along n)
        {
            int i = k0 + b_row;
            if (i < IDIM) {
                const float* p = W + (long long)i * NW + n0 + b_col;
                float4 v0 = *reinterpret_cast<const float4*>(p);
                float4 v1 = *reinterpret_cast<const float4*>(p + 4);
                *reinterpret_cast<float4*>(&Bs[b_row][b_col])     = v0;
                *reinterpret_cast<float4*>(&Bs[b_row][b_col + 4]) = v1;
            } else {
                float4 zz = make_float4(0.f, 0.f, 0.f, 0.f);
                *reinterpret_cast<float4*>(&Bs[b_row][b_col])     = zz;
                *reinterpret_cast<float4*>(&Bs[b_row][b_col + 4]) = zz;
            }
        }
        __syncthreads();
        mma_step(As, Bs, acc, tx, ty);
        __syncthreads();
    }

#pragma unroll
    for (int i = 0; i < 8; i++) {
        float* crow = g_Xw + (long long)(m0 + ty * 8 + i) * NW + n0 + tx * 8;
        ulonglong2 r0; r0.x = acc[i][0]; r0.y = acc[i][1];
        ulonglong2 r1; r1.x = acc[i][2]; r1.y = acc[i][3];
        *reinterpret_cast<ulonglong2*>(crow)     = r0;
        *reinterpret_cast<ulonglong2*>(crow + 4) = r1;
    }
}

// ----------------------------------------------------------------------------
// k2: T[bx] = z[b] @ Xw[bx].  grid = (5 n-tiles, 1024 bx). N=513 -> guarded.
// ----------------------------------------------------------------------------
__global__ __launch_bounds__(256, 2)
void triaffine_k2(const float* __restrict__ zin)
{
    __shared__ float As[BK][BM];
    __shared__ float Bs[BK][BN];
    const int bx = blockIdx.y;
    const int b  = bx >> 7;
    const int n0 = blockIdx.x * BN;
    const int tid = threadIdx.x;
    const int tx = tid & 15, ty = tid >> 4;
    const int a_row = tid >> 1;
    const int a_k   = (tid & 1) * 8;
    const int b_row = tid >> 4;
    const int b_col = (tid & 15) * 8;

    unsigned long long acc[8][4];
#pragma unroll
    for (int i = 0; i < 8; i++)
#pragma unroll
        for (int j = 0; j < 4; j++) acc[i][j] = 0ull;

    const long long zrow  = ((long long)b * 128 + a_row) * NIN;
    const float*    Bbase = g_Xw + (long long)bx * NW;

    for (int k0 = 0; k0 < NIN; k0 += BK) {
        float4 v0 = *reinterpret_cast<const float4*>(zin + zrow + k0 + a_k);
        float4 v1 = *reinterpret_cast<const float4*>(zin + zrow + k0 + a_k + 4);
        As[a_k + 0][a_row] = v0.x; As[a_k + 1][a_row] = v0.y;
        As[a_k + 2][a_row] = v0.z; As[a_k + 3][a_row] = v0.w;
        As[a_k + 4][a_row] = v1.x; As[a_k + 5][a_row] = v1.y;
        As[a_k + 6][a_row] = v1.z; As[a_k + 7][a_row] = v1.w;
        {
            const float* p = Bbase + (long long)(k0 + b_row) * IDIM + n0 + b_col;
#pragma unroll
            for (int u = 0; u < 8; u++) {
                int n = n0 + b_col + u;
                Bs[b_row][b_col + u] = (n < IDIM) ? p[u] : 0.0f;
            }
        }
        __syncthreads();
        mma_step(As, Bs, acc, tx, ty);
        __syncthreads();
    }

    float* Tb = g_T + (long long)bx * TROW;
#pragma unroll
    for (int i = 0; i < 8; i++) {
        int zz = ty * 8 + i;
#pragma unroll
        for (int j = 0; j < 4; j++) {
            int c0 = n0 + tx * 8 + 2 * j;
            float lo = __uint_as_float((unsigned)(acc[i][j] & 0xffffffffull));
            float hi = __uint_as_float((unsigned)(acc[i][j] >> 32));
            if (c0 < IDIM)     Tb[zz * IDIM + c0]     = lo;
            if (c0 + 1 < IDIM) Tb[zz * IDIM + c0 + 1] = hi;
        }
    }
}

// ----------------------------------------------------------------------------
// k3: out[b,z,xx,y] = T[bx] @ yb[b]^T.  grid = 1024 bx, one 128x128 tile each.
// ----------------------------------------------------------------------------
__global__ __launch_bounds__(256, 2)
void triaffine_k3(const float* __restrict__ yin, float* __restrict__ out)
{
    __shared__ float As[BK][BM];
    __shared__ float Bs[BK][BN];
    const int bx = blockIdx.x;
    const int b  = bx >> 7;
    const int xx = bx & 127;
    const int tid = threadIdx.x;
    const int tx = tid & 15, ty = tid >> 4;
    const int a_row = tid >> 1;
    const int a_k   = (tid & 1) * 8;

    unsigned long long acc[8][4];
#pragma unroll
    for (int i = 0; i < 8; i++)
#pragma unroll
        for (int j = 0; j < 4; j++) acc[i][j] = 0ull;

    const float*    Ta   = g_T + (long long)bx * TROW + (long long)a_row * IDIM;
    const long long yrow = ((long long)b * 128 + a_row) * NIN;

    for (int k0 = 0; k0 < IDIM; k0 += BK) {
#pragma unroll
        for (int u = 0; u < 8; u++) {
            int j = k0 + a_k + u;
            As[a_k + u][a_row] = (j < IDIM) ? Ta[j] : 0.0f;
            float bv;
            if (j < NIN)       bv = yin[yrow + j];
            else               bv = (j == NIN) ? 1.0f : 0.0f;
            Bs[a_k + u][a_row] = bv;
        }
        __syncthreads();
        mma_step(As, Bs, acc, tx, ty);
        __syncthreads();
    }

#pragma unroll
    for (int i = 0; i < 8; i++) {
        int zz = ty * 8 + i;
        float* o = out + ((((long long)b * 128 + zz) * 128) + xx) * 128 + tx * 8;
        ulonglong2 r0; r0.x = acc[i][0]; r0.y = acc[i][1];
        ulonglong2 r1; r1.x = acc[i][2]; r1.y = acc[i][3];
        *reinterpret_cast<ulonglong2*>(o)     = r0;
        *reinterpret_cast<ulonglong2*>(o + 4) = r1;
    }
}

// ----------------------------------------------------------------------------

extern "C" void kernel_launch(void* const* d_in, const int* in_sizes, int n_in,
                              void* d_out, int out_size)
{
    const float* x = (const float*)d_in[0];
    const float* y = (const float*)d_in[1];
    const float* z = (const float*)d_in[2];
    const float* w = (const float*)d_in[3];
    float* out = (float*)d_out;

    // Stage 1: Xw = xb_all @ W   (276 GFLOP)
    triaffine_k1<<<dim3(8, 2052), 256>>>(x, w);
    // Stage 2: T[bx] = z[b] @ Xw[bx]   (69 GFLOP)
    triaffine_k2<<<dim3(5, 1024), 256>>>(z);
    // Stage 3: out = T @ yb^T   (17 GFLOP)
    triaffine_k3<<<dim3(1024), 256>>>(y, out);
}